// round 5
// baseline (speedup 1.0000x reference)
#include <cuda_runtime.h>

// Problem constants (fixed by the dataset)
#define NMAX 100000
#define EMAX 1600000
#define D    64
#define G    64

// ---- device scratch (no allocations allowed) ----
__device__ float g_deg [NMAX];
__device__ float g_dinv[NMAX];
__device__ float g_norm[EMAX];
__device__ float g_bufA[NMAX * D];
__device__ float g_bufB[NMAX * D];
__device__ float g_bufC[NMAX * D];
__device__ float g_pool[G * D];
__device__ float g_cnt [G];

// ------------------------------------------------------------------
// K0: init deg=1 (self-loop), zero pool accumulators
// ------------------------------------------------------------------
__global__ void k_init(int N) {
    int i = blockIdx.x * blockDim.x + threadIdx.x;
    if (i < N)      g_deg[i]  = 1.0f;
    if (i < G * D)  g_pool[i] = 0.0f;
    if (i < G)      g_cnt[i]  = 0.0f;
}

// ------------------------------------------------------------------
// K1: degree histogram over edge targets (col)
// ------------------------------------------------------------------
__global__ void k_deg(const int* __restrict__ col, int E) {
    int e = blockIdx.x * blockDim.x + threadIdx.x;
    if (e < E) atomicAdd(&g_deg[col[e]], 1.0f);
}

// ------------------------------------------------------------------
// K2: dinv = rsqrt(deg)   (deg >= 1 always, self-loop)
// ------------------------------------------------------------------
__global__ void k_dinv(int N) {
    int i = blockIdx.x * blockDim.x + threadIdx.x;
    if (i < N) g_dinv[i] = rsqrtf(g_deg[i]);
}

// ------------------------------------------------------------------
// K3: per-edge norm = dinv[row]*dinv[col]
// ------------------------------------------------------------------
__global__ void k_norm(const int* __restrict__ row, const int* __restrict__ col, int E) {
    int e = blockIdx.x * blockDim.x + threadIdx.x;
    if (e < E) g_norm[e] = g_dinv[row[e]] * g_dinv[col[e]];
}

// ------------------------------------------------------------------
// K4: embedding gather x[i][d] = emb[node_types[i]][d]
// ------------------------------------------------------------------
__global__ void k_embed(const int* __restrict__ nt, const float* __restrict__ emb, int N) {
    int t = blockIdx.x * blockDim.x + threadIdx.x;
    if (t < N * D) {
        int i = t >> 6;
        int d = t & (D - 1);
        g_bufA[t] = emb[nt[i] * D + d];
    }
}

// ------------------------------------------------------------------
// K_mm: h = relu?(x) @ W, and initialize y = b + h * dinv^2 (self-loop term)
//   block = 256 threads -> 4 node rows, W staged in smem
// ------------------------------------------------------------------
__global__ void k_mm(const float* __restrict__ x, const float* __restrict__ W,
                     const float* __restrict__ b,
                     float* __restrict__ h, float* __restrict__ y,
                     int N, int relu_in) {
    __shared__ float sW[D * D];
    __shared__ float sx[4][D];
    int tid = threadIdx.x;
    for (int i = tid; i < D * D; i += 256) sW[i] = W[i];

    int r = tid >> 6;          // 0..3  row within block
    int d = tid & (D - 1);     // 0..63
    int n = blockIdx.x * 4 + r;
    if (n < N) {
        float v = x[n * D + d];
        sx[r][d] = relu_in ? fmaxf(v, 0.0f) : v;
    }
    __syncthreads();
    if (n < N) {
        float acc = 0.0f;
#pragma unroll
        for (int k = 0; k < D; k++)
            acc = fmaf(sx[r][k], sW[k * D + d], acc);
        h[n * D + d] = acc;
        float di = g_dinv[n];
        y[n * D + d] = b[d] + acc * di * di;
    }
}

// ------------------------------------------------------------------
// K_scatter: y[col] += h[row] * norm
//   16 threads per edge, float4 gather, ONE red.global.add.v4.f32 per thread
//   (4x fewer reduction ops vs scalar atomicAdd; no return value needed)
// ------------------------------------------------------------------
__global__ void k_scatter(const int* __restrict__ row, const int* __restrict__ col,
                          const float* __restrict__ h, float* __restrict__ y, int E) {
    long long t = (long long)blockIdx.x * blockDim.x + threadIdx.x;
    int e = (int)(t >> 4);
    if (e >= E) return;
    int q  = (int)(t & 15);
    int rs = row[e];
    int cs = col[e];
    float w = g_norm[e];
    float4 hv = *reinterpret_cast<const float4*>(h + rs * D + q * 4);
    float* yp = y + cs * D + q * 4;
    asm volatile("red.global.add.v4.f32 [%0], {%1, %2, %3, %4};"
                 :: "l"(yp), "f"(hv.x * w), "f"(hv.y * w), "f"(hv.z * w), "f"(hv.w * w)
                 : "memory");
}

// ------------------------------------------------------------------
// K_pool: segment mean accumulation (batch is sorted -> register-accumulate,
//         flush to global on graph change). 64 threads/block, CHUNK nodes/block.
// ------------------------------------------------------------------
#define POOL_CHUNK 256
__global__ void k_pool(const float* __restrict__ x, const int* __restrict__ batch, int N) {
    int d = threadIdx.x;              // 0..63
    int s = blockIdx.x * POOL_CHUNK;
    int eN = min(s + POOL_CHUNK, N);
    float acc = 0.0f, cnt = 0.0f;
    int cur = -1;
    for (int n = s; n < eN; n++) {
        int bg = batch[n];
        if (bg != cur) {
            if (cur >= 0) {
                atomicAdd(&g_pool[cur * D + d], acc);
                if (d == 0) atomicAdd(&g_cnt[cur], cnt);
            }
            cur = bg; acc = 0.0f; cnt = 0.0f;
        }
        acc += x[n * D + d];
        cnt += 1.0f;
    }
    if (cur >= 0) {
        atomicAdd(&g_pool[cur * D + d], acc);
        if (d == 0) atomicAdd(&g_cnt[cur], cnt);
    }
}

// ------------------------------------------------------------------
// K_final: pooled = sum/max(cnt,1); out = pooled / ||pooled||_2
//   2 blocks x 32 warps; warp w handles row (blockIdx*32 + w)
// ------------------------------------------------------------------
__global__ void k_final(float* __restrict__ out) {
    int r    = blockIdx.x * 32 + (threadIdx.x >> 5);
    int lane = threadIdx.x & 31;
    float c  = fmaxf(g_cnt[r], 1.0f);
    float v0 = g_pool[r * D + lane]      / c;
    float v1 = g_pool[r * D + 32 + lane] / c;
    float ss = v0 * v0 + v1 * v1;
#pragma unroll
    for (int o = 16; o > 0; o >>= 1) ss += __shfl_xor_sync(0xFFFFFFFFu, ss, o);
    float inv = rsqrtf(ss);
    out[r * D + lane]      = v0 * inv;
    out[r * D + 32 + lane] = v1 * inv;
}

// ------------------------------------------------------------------
// Host launcher
// ------------------------------------------------------------------
extern "C" void kernel_launch(void* const* d_in, const int* in_sizes, int n_in,
                              void* d_out, int out_size) {
    const int*   node_types = (const int*)  d_in[0];
    const int*   edge_index = (const int*)  d_in[1];
    const int*   batch      = (const int*)  d_in[2];
    const float* emb_table  = (const float*)d_in[3];
    const float* W1 = (const float*)d_in[4];
    const float* b1 = (const float*)d_in[5];
    const float* W2 = (const float*)d_in[6];
    const float* b2 = (const float*)d_in[7];
    const float* W3 = (const float*)d_in[8];
    const float* b3 = (const float*)d_in[9];
    float* out = (float*)d_out;

    const int N = in_sizes[0];
    const int E = in_sizes[1] / 2;
    const int* row = edge_index;        // edge_index[0, :]
    const int* col = edge_index + E;    // edge_index[1, :]

    float* bufA; cudaGetSymbolAddress((void**)&bufA, g_bufA);
    float* bufB; cudaGetSymbolAddress((void**)&bufB, g_bufB);
    float* bufC; cudaGetSymbolAddress((void**)&bufC, g_bufC);

    const int T = 256;
    // precompute normalization
    k_init <<<(N + T - 1) / T, T>>>(N);
    k_deg  <<<(E + T - 1) / T, T>>>(col, E);
    k_dinv <<<(N + T - 1) / T, T>>>(N);
    k_norm <<<(E + T - 1) / T, T>>>(row, col, E);
    k_embed<<<(N * D + T - 1) / T, T>>>(node_types, emb_table, N);

    long long sc_threads = (long long)E * 16;
    int sc_blocks = (int)((sc_threads + T - 1) / T);
    int mm_blocks = (N + 3) / 4;

    // layer 1: A -> h(B) -> y(C)
    k_mm     <<<mm_blocks, T>>>(bufA, W1, b1, bufB, bufC, N, 0);
    k_scatter<<<sc_blocks, T>>>(row, col, bufB, bufC, E);
    // layer 2: relu(C) -> h(B) -> y(A)
    k_mm     <<<mm_blocks, T>>>(bufC, W2, b2, bufB, bufA, N, 1);
    k_scatter<<<sc_blocks, T>>>(row, col, bufB, bufA, E);
    // layer 3: relu(A) -> h(B) -> y(C)
    k_mm     <<<mm_blocks, T>>>(bufA, W3, b3, bufB, bufC, N, 1);
    k_scatter<<<sc_blocks, T>>>(row, col, bufB, bufC, E);

    // mean-pool + L2 normalize
    k_pool <<<(N + POOL_CHUNK - 1) / POOL_CHUNK, 64>>>(bufC, batch, N);
    k_final<<<2, 1024>>>(out);
}

// round 6
// speedup vs baseline: 1.3043x; 1.3043x over previous
#include <cuda_runtime.h>

// Problem constants (fixed by the dataset)
#define NMAX 100000
#define EMAX 1600000
#define D    64
#define G    64

// ---- device scratch (no allocations allowed) ----
__device__ int   g_degi  [NMAX];        // in-degree (real edges only)
__device__ float g_dinv  [NMAX];        // rsqrt(deg+1)
__device__ int   g_off   [NMAX + 1];    // CSR row offsets (by destination)
__device__ int   g_cursor[NMAX];        // build cursors
__device__ int   g_bsum  [256];         // scan block partials
__device__ int   g_csrc  [EMAX];        // CSR: source node per edge slot
__device__ float g_bufA  [NMAX * D];
__device__ float g_bufB  [NMAX * D];    // hs = (x@W)*dinv
__device__ float g_bufC  [NMAX * D];
__device__ float g_pool  [G * D];
__device__ float g_cnt   [G];

// ------------------------------------------------------------------
// K_init: zero degree counts + pool accumulators
// ------------------------------------------------------------------
__global__ void k_init(int N) {
    int i = blockIdx.x * blockDim.x + threadIdx.x;
    if (i < N)     g_degi[i] = 0;
    if (i < G * D) g_pool[i] = 0.0f;
    if (i < G)     g_cnt[i]  = 0.0f;
}

// ------------------------------------------------------------------
// K_hist: in-degree histogram over edge targets (col)
// ------------------------------------------------------------------
__global__ void k_hist(const int* __restrict__ col, int E) {
    int e = blockIdx.x * blockDim.x + threadIdx.x;
    if (e < E) atomicAdd(&g_degi[col[e]], 1);
}

// ------------------------------------------------------------------
// K_dinv: dinv = rsqrt(deg + 1)   (+1 = self loop)
// ------------------------------------------------------------------
__global__ void k_dinv(int N) {
    int i = blockIdx.x * blockDim.x + threadIdx.x;
    if (i < N) g_dinv[i] = rsqrtf((float)(g_degi[i] + 1));
}

// ------------------------------------------------------------------
// Scan pass 1: per-block (1024 elems) exclusive scan of g_degi -> g_off,
//              block totals -> g_bsum
// ------------------------------------------------------------------
__global__ void k_scan1(int N) {
    __shared__ int sh[256];
    int t = threadIdx.x;
    int base = blockIdx.x * 1024;
    int v[4];
    int sum = 0;
#pragma unroll
    for (int j = 0; j < 4; j++) {
        int idx = base + t * 4 + j;
        v[j] = (idx < N) ? g_degi[idx] : 0;
        sum += v[j];
    }
    sh[t] = sum;
    __syncthreads();
    for (int o = 1; o < 256; o <<= 1) {
        int x = (t >= o) ? sh[t - o] : 0;
        __syncthreads();
        sh[t] += x;
        __syncthreads();
    }
    int excl = sh[t] - sum;
    if (t == 255) g_bsum[blockIdx.x] = sh[255];
    int run = excl;
#pragma unroll
    for (int j = 0; j < 4; j++) {
        int idx = base + t * 4 + j;
        if (idx < N) g_off[idx] = run;
        run += v[j];
    }
}

// ------------------------------------------------------------------
// Scan pass 2: single block exclusive-scans the block partials (B <= 256)
// ------------------------------------------------------------------
__global__ void k_scan2(int B) {
    __shared__ int sh[256];
    int t = threadIdx.x;
    int v = (t < B) ? g_bsum[t] : 0;
    sh[t] = v;
    __syncthreads();
    for (int o = 1; o < 256; o <<= 1) {
        int x = (t >= o) ? sh[t - o] : 0;
        __syncthreads();
        sh[t] += x;
        __syncthreads();
    }
    if (t < B) g_bsum[t] = sh[t] - v;
}

// ------------------------------------------------------------------
// Scan pass 3: add block base, init cursors, set sentinel off[N]=E
// ------------------------------------------------------------------
__global__ void k_scan3(int N, int E) {
    int i = blockIdx.x * blockDim.x + threadIdx.x;
    if (i < N) {
        int o = g_off[i] + g_bsum[i >> 10];
        g_off[i]    = o;
        g_cursor[i] = o;
    }
    if (i == 0) g_off[N] = E;
}

// ------------------------------------------------------------------
// K_build: fill CSR source array via per-destination cursors
// ------------------------------------------------------------------
__global__ void k_build(const int* __restrict__ row, const int* __restrict__ col, int E) {
    int e = blockIdx.x * blockDim.x + threadIdx.x;
    if (e < E) {
        int p = atomicAdd(&g_cursor[col[e]], 1);
        g_csrc[p] = row[e];
    }
}

// ------------------------------------------------------------------
// K_mm: hs = (relu?(x) @ W) * dinv       (dinv[src] folded into rows)
//   If nt != nullptr, x row = emb_table[nt[n]] (fused embedding gather).
//   block = 256 threads -> 4 node rows, W staged in smem
// ------------------------------------------------------------------
__global__ void k_mm(const float* __restrict__ x, const int* __restrict__ nt,
                     const float* __restrict__ emb,
                     const float* __restrict__ W,
                     float* __restrict__ hs,
                     int N, int relu_in) {
    __shared__ float sW[D * D];
    __shared__ float sx[4][D];
    int tid = threadIdx.x;
    for (int i = tid; i < D * D; i += 256) sW[i] = W[i];

    int r = tid >> 6;          // 0..3  row within block
    int d = tid & (D - 1);     // 0..63
    int n = blockIdx.x * 4 + r;
    if (n < N) {
        float v = nt ? emb[nt[n] * D + d] : x[n * D + d];
        sx[r][d] = relu_in ? fmaxf(v, 0.0f) : v;
    }
    __syncthreads();
    if (n < N) {
        float acc = 0.0f;
#pragma unroll
        for (int k = 0; k < D; k++)
            acc = fmaf(sx[r][k], sW[k * D + d], acc);
        hs[n * D + d] = acc * g_dinv[n];
    }
}

// ------------------------------------------------------------------
// K_agg: y[n] = b + dinv[n] * ( sum_{src in in(n)} hs[src] + hs[n] )
//   warp per node, float2 per lane, 2-wide unrolled gather for MLP.
//   Pure gather + one coalesced store: NO atomics.
// ------------------------------------------------------------------
__global__ void k_agg(const float* __restrict__ hs, const float* __restrict__ b,
                      float* __restrict__ y, int N) {
    int w    = (blockIdx.x * blockDim.x + threadIdx.x) >> 5;
    int lane = threadIdx.x & 31;
    if (w >= N) return;
    int start = g_off[w];
    int end   = g_off[w + 1];
    const float2* H = (const float2*)hs;
    float ax = 0.0f, ay = 0.0f;
    int i = start;
    for (; i + 1 < end; i += 2) {
        int s0 = g_csrc[i];
        int s1 = g_csrc[i + 1];
        float2 v0 = H[s0 * 32 + lane];
        float2 v1 = H[s1 * 32 + lane];
        ax += v0.x + v1.x;
        ay += v0.y + v1.y;
    }
    if (i < end) {
        int s = g_csrc[i];
        float2 v = H[s * 32 + lane];
        ax += v.x;
        ay += v.y;
    }
    float2 hv = H[w * 32 + lane];
    float di  = g_dinv[w];
    float2 o;
    o.x = b[lane * 2]     + di * (ax + hv.x);
    o.y = b[lane * 2 + 1] + di * (ay + hv.y);
    ((float2*)y)[w * 32 + lane] = o;
}

// ------------------------------------------------------------------
// K_pool: segment mean accumulation (batch is sorted -> register-accumulate,
//         flush to global on graph change). 64 threads/block.
// ------------------------------------------------------------------
#define POOL_CHUNK 256
__global__ void k_pool(const float* __restrict__ x, const int* __restrict__ batch, int N) {
    int d = threadIdx.x;              // 0..63
    int s = blockIdx.x * POOL_CHUNK;
    int eN = min(s + POOL_CHUNK, N);
    float acc = 0.0f, cnt = 0.0f;
    int cur = -1;
    for (int n = s; n < eN; n++) {
        int bg = batch[n];
        if (bg != cur) {
            if (cur >= 0) {
                atomicAdd(&g_pool[cur * D + d], acc);
                if (d == 0) atomicAdd(&g_cnt[cur], cnt);
            }
            cur = bg; acc = 0.0f; cnt = 0.0f;
        }
        acc += x[n * D + d];
        cnt += 1.0f;
    }
    if (cur >= 0) {
        atomicAdd(&g_pool[cur * D + d], acc);
        if (d == 0) atomicAdd(&g_cnt[cur], cnt);
    }
}

// ------------------------------------------------------------------
// K_final: pooled = sum/max(cnt,1); out = pooled / ||pooled||_2
// ------------------------------------------------------------------
__global__ void k_final(float* __restrict__ out) {
    int r    = blockIdx.x * 32 + (threadIdx.x >> 5);
    int lane = threadIdx.x & 31;
    float c  = fmaxf(g_cnt[r], 1.0f);
    float v0 = g_pool[r * D + lane]      / c;
    float v1 = g_pool[r * D + 32 + lane] / c;
    float ss = v0 * v0 + v1 * v1;
#pragma unroll
    for (int o = 16; o > 0; o >>= 1) ss += __shfl_xor_sync(0xFFFFFFFFu, ss, o);
    float inv = rsqrtf(ss);
    out[r * D + lane]      = v0 * inv;
    out[r * D + 32 + lane] = v1 * inv;
}

// ------------------------------------------------------------------
// Host launcher
// ------------------------------------------------------------------
extern "C" void kernel_launch(void* const* d_in, const int* in_sizes, int n_in,
                              void* d_out, int out_size) {
    const int*   node_types = (const int*)  d_in[0];
    const int*   edge_index = (const int*)  d_in[1];
    const int*   batch      = (const int*)  d_in[2];
    const float* emb_table  = (const float*)d_in[3];
    const float* W1 = (const float*)d_in[4];
    // b1 = d_in[5]
    const float* W2 = (const float*)d_in[6];
    // b2 = d_in[7]
    const float* W3 = (const float*)d_in[8];
    // b3 = d_in[9]
    const float* b1 = (const float*)d_in[5];
    const float* b2 = (const float*)d_in[7];
    const float* b3 = (const float*)d_in[9];
    float* out = (float*)d_out;

    const int N = in_sizes[0];
    const int E = in_sizes[1] / 2;
    const int* row = edge_index;        // edge_index[0, :]
    const int* col = edge_index + E;    // edge_index[1, :]

    float* bufA; cudaGetSymbolAddress((void**)&bufA, g_bufA);
    float* bufB; cudaGetSymbolAddress((void**)&bufB, g_bufB);
    float* bufC; cudaGetSymbolAddress((void**)&bufC, g_bufC);

    const int T = 256;
    const int scanB = (N + 1023) / 1024;

    // ---- precompute: degrees, dinv, CSR-by-destination ----
    k_init <<<(N + T - 1) / T, T>>>(N);
    k_hist <<<(E + T - 1) / T, T>>>(col, E);
    k_dinv <<<(N + T - 1) / T, T>>>(N);
    k_scan1<<<scanB, 256>>>(N);
    k_scan2<<<1, 256>>>(scanB);
    k_scan3<<<(N + T - 1) / T, T>>>(N, E);
    k_build<<<(E + T - 1) / T, T>>>(row, col, E);

    int mm_blocks  = (N + 3) / 4;
    int agg_blocks = (N + 7) / 8;       // 8 warps/block, warp per node

    // layer 1: emb-gather -> hs(B); agg -> y(C)
    k_mm <<<mm_blocks, T>>>(nullptr, node_types, emb_table, W1, bufB, N, 0);
    k_agg<<<agg_blocks, T>>>(bufB, b1, bufC, N);
    // layer 2: relu(C) -> hs(B); agg -> y(A)
    k_mm <<<mm_blocks, T>>>(bufC, nullptr, nullptr, W2, bufB, N, 1);
    k_agg<<<agg_blocks, T>>>(bufB, b2, bufA, N);
    // layer 3: relu(A) -> hs(B); agg -> y(C)
    k_mm <<<mm_blocks, T>>>(bufA, nullptr, nullptr, W3, bufB, N, 1);
    k_agg<<<agg_blocks, T>>>(bufB, b3, bufC, N);

    // mean-pool + L2 normalize
    k_pool <<<(N + POOL_CHUNK - 1) / POOL_CHUNK, 64>>>(bufC, batch, N);
    k_final<<<2, 1024>>>(out);
}

// round 10
// speedup vs baseline: 2.5594x; 1.9623x over previous
#include <cuda_runtime.h>

// Problem constants (fixed by the dataset)
#define NMAX 100000
#define EMAX 1600000
#define D    64
#define G    64

// ---- device scratch (no allocations allowed) ----
__device__ int   g_degi  [NMAX];        // in-degree (real edges only)
__device__ float g_dinv  [NMAX];        // rsqrt(deg+1)
__device__ int   g_off   [NMAX + 1];    // CSR row offsets (by destination)
__device__ int   g_cursor[NMAX];        // build cursors
__device__ int   g_bsum  [256];         // scan block partials
__device__ int   g_csrc  [EMAX];        // CSR: source node per edge slot
__device__ float g_bufA  [NMAX * D];
__device__ float g_bufB  [NMAX * D];    // hs = (x@W)*dinv
__device__ float g_bufC  [NMAX * D];
__device__ float g_pool  [G * D];
__device__ float g_cnt   [G];

// ------------------------------------------------------------------
// K_hist: in-degree histogram over edge targets (col)
// ------------------------------------------------------------------
__global__ void k_hist(const int* __restrict__ col, int E) {
    int e = blockIdx.x * blockDim.x + threadIdx.x;
    if (e < E) atomicAdd(&g_degi[col[e]], 1);
}

// ------------------------------------------------------------------
// Scan pass 1: per-block (1024 elems) exclusive scan of g_degi -> g_off,
//              block totals -> g_bsum. Also computes dinv = rsqrt(deg+1).
// ------------------------------------------------------------------
__global__ void k_scan1(int N) {
    __shared__ int sh[256];
    int t = threadIdx.x;
    int base = blockIdx.x * 1024;
    int v[4];
    int sum = 0;
#pragma unroll
    for (int j = 0; j < 4; j++) {
        int idx = base + t * 4 + j;
        v[j] = (idx < N) ? g_degi[idx] : 0;
        if (idx < N) g_dinv[idx] = rsqrtf((float)(v[j] + 1));
        sum += v[j];
    }
    sh[t] = sum;
    __syncthreads();
    for (int o = 1; o < 256; o <<= 1) {
        int x = (t >= o) ? sh[t - o] : 0;
        __syncthreads();
        sh[t] += x;
        __syncthreads();
    }
    int excl = sh[t] - sum;
    if (t == 255) g_bsum[blockIdx.x] = sh[255];
    int run = excl;
#pragma unroll
    for (int j = 0; j < 4; j++) {
        int idx = base + t * 4 + j;
        if (idx < N) g_off[idx] = run;
        run += v[j];
    }
}

// ------------------------------------------------------------------
// Scan pass 2: single block exclusive-scans the block partials (B <= 256)
// ------------------------------------------------------------------
__global__ void k_scan2(int B) {
    __shared__ int sh[256];
    int t = threadIdx.x;
    int v = (t < B) ? g_bsum[t] : 0;
    sh[t] = v;
    __syncthreads();
    for (int o = 1; o < 256; o <<= 1) {
        int x = (t >= o) ? sh[t - o] : 0;
        __syncthreads();
        sh[t] += x;
        __syncthreads();
    }
    if (t < B) g_bsum[t] = sh[t] - v;
}

// ------------------------------------------------------------------
// Scan pass 3: add block base, init cursors, set sentinel off[N]=E
// ------------------------------------------------------------------
__global__ void k_scan3(int N, int E) {
    int i = blockIdx.x * blockDim.x + threadIdx.x;
    if (i < N) {
        int o = g_off[i] + g_bsum[i >> 10];
        g_off[i]    = o;
        g_cursor[i] = o;
    }
    if (i == 0) g_off[N] = E;
}

// ------------------------------------------------------------------
// K_build: fill CSR source array via per-destination cursors
// ------------------------------------------------------------------
__global__ void k_build(const int* __restrict__ row, const int* __restrict__ col, int E) {
    int e = blockIdx.x * blockDim.x + threadIdx.x;
    if (e < E) {
        int p = atomicAdd(&g_cursor[col[e]], 1);
        g_csrc[p] = row[e];
    }
}

// ------------------------------------------------------------------
// K_mm v2: hs = (relu?(x) @ W) * dinv
//   16 rows/block, 256 threads; thread = (row, 4-col group).
//   Inner loop: 1 LDS.128 (W) + 1 LDS.32 broadcast (x) per 4 FFMA.
//   If nt != nullptr, x row = emb_table[nt[n]] (fused embedding gather).
// ------------------------------------------------------------------
__global__ void __launch_bounds__(256)
k_mm(const float* __restrict__ x, const int* __restrict__ nt,
     const float* __restrict__ emb,
     const float* __restrict__ W,
     float* __restrict__ hs,
     int N, int relu_in) {
    __shared__ float sW[D * D];
    __shared__ float sx[16][D];
    int tid = threadIdx.x;

    float4* sW4 = (float4*)sW;
    const float4* W4 = (const float4*)W;
    for (int i = tid; i < D * D / 4; i += 256) sW4[i] = W4[i];

    int base = blockIdx.x * 16;
    for (int j = tid; j < 16 * D; j += 256) {
        int r = j >> 6, d = j & 63;
        int n = base + r;
        float v = 0.0f;
        if (n < N) v = nt ? emb[nt[n] * D + d] : x[n * D + d];
        sx[r][d] = relu_in ? fmaxf(v, 0.0f) : v;
    }
    __syncthreads();

    int r  = tid >> 4;     // 0..15 row
    int dq = tid & 15;     // 0..15 column quad
    int n  = base + r;
    if (n >= N) return;
    float4 acc = make_float4(0.f, 0.f, 0.f, 0.f);
#pragma unroll
    for (int k = 0; k < D; k++) {
        float bv = sx[r][k];
        float4 w = sW4[k * 16 + dq];
        acc.x = fmaf(bv, w.x, acc.x);
        acc.y = fmaf(bv, w.y, acc.y);
        acc.z = fmaf(bv, w.z, acc.z);
        acc.w = fmaf(bv, w.w, acc.w);
    }
    float di = g_dinv[n];
    acc.x *= di; acc.y *= di; acc.z *= di; acc.w *= di;
    ((float4*)hs)[n * 16 + dq] = acc;
}

// ------------------------------------------------------------------
// K_agg v2: y[n] = b + dinv[n] * ( sum_{src in in(n)} hs[src] + hs[n] )
//   warp per node, float2 per lane; 4-wide unrolled gather (MLP=4),
//   dual accumulators. Pure gather + one coalesced store: NO atomics.
// ------------------------------------------------------------------
__global__ void __launch_bounds__(256)
k_agg(const float* __restrict__ hs, const float* __restrict__ b,
      float* __restrict__ y, int N) {
    int w    = (blockIdx.x * blockDim.x + threadIdx.x) >> 5;
    int lane = threadIdx.x & 31;
    if (w >= N) return;
    int i   = g_off[w];
    int end = g_off[w + 1];
    const float2* H = (const float2*)hs;
    float ax0 = 0.f, ay0 = 0.f, ax1 = 0.f, ay1 = 0.f;
    for (; i + 3 < end; i += 4) {
        int s0 = __ldg(&g_csrc[i]);
        int s1 = __ldg(&g_csrc[i + 1]);
        int s2 = __ldg(&g_csrc[i + 2]);
        int s3 = __ldg(&g_csrc[i + 3]);
        float2 v0 = H[s0 * 32 + lane];
        float2 v1 = H[s1 * 32 + lane];
        float2 v2 = H[s2 * 32 + lane];
        float2 v3 = H[s3 * 32 + lane];
        ax0 += v0.x + v1.x;  ay0 += v0.y + v1.y;
        ax1 += v2.x + v3.x;  ay1 += v2.y + v3.y;
    }
    for (; i < end; i++) {
        int s = __ldg(&g_csrc[i]);
        float2 v = H[s * 32 + lane];
        ax0 += v.x;  ay0 += v.y;
    }
    float2 hv = H[w * 32 + lane];
    float di  = g_dinv[w];
    float2 o;
    o.x = b[lane * 2]     + di * (ax0 + ax1 + hv.x);
    o.y = b[lane * 2 + 1] + di * (ay0 + ay1 + hv.y);
    ((float2*)y)[w * 32 + lane] = o;
}

// ------------------------------------------------------------------
// K_pool: segment mean accumulation (batch is sorted -> register-accumulate,
//         flush to global on graph change). 64 threads/block.
// ------------------------------------------------------------------
#define POOL_CHUNK 256
__global__ void k_pool(const float* __restrict__ x, const int* __restrict__ batch, int N) {
    int d = threadIdx.x;              // 0..63
    int s = blockIdx.x * POOL_CHUNK;
    int eN = min(s + POOL_CHUNK, N);
    float acc = 0.0f, cnt = 0.0f;
    int cur = -1;
    for (int n = s; n < eN; n++) {
        int bg = batch[n];
        if (bg != cur) {
            if (cur >= 0) {
                atomicAdd(&g_pool[cur * D + d], acc);
                if (d == 0) atomicAdd(&g_cnt[cur], cnt);
            }
            cur = bg; acc = 0.0f; cnt = 0.0f;
        }
        acc += x[n * D + d];
        cnt += 1.0f;
    }
    if (cur >= 0) {
        atomicAdd(&g_pool[cur * D + d], acc);
        if (d == 0) atomicAdd(&g_cnt[cur], cnt);
    }
}

// ------------------------------------------------------------------
// K_final: pooled = sum/max(cnt,1); out = pooled / ||pooled||_2
// ------------------------------------------------------------------
__global__ void k_final(float* __restrict__ out) {
    int r    = blockIdx.x * 32 + (threadIdx.x >> 5);
    int lane = threadIdx.x & 31;
    float c  = fmaxf(g_cnt[r], 1.0f);
    float v0 = g_pool[r * D + lane]      / c;
    float v1 = g_pool[r * D + 32 + lane] / c;
    float ss = v0 * v0 + v1 * v1;
#pragma unroll
    for (int o = 16; o > 0; o >>= 1) ss += __shfl_xor_sync(0xFFFFFFFFu, ss, o);
    float inv = rsqrtf(ss);
    out[r * D + lane]      = v0 * inv;
    out[r * D + 32 + lane] = v1 * inv;
}

// ------------------------------------------------------------------
// Host launcher
// ------------------------------------------------------------------
extern "C" void kernel_launch(void* const* d_in, const int* in_sizes, int n_in,
                              void* d_out, int out_size) {
    const int*   node_types = (const int*)  d_in[0];
    const int*   edge_index = (const int*)  d_in[1];
    const int*   batch      = (const int*)  d_in[2];
    const float* emb_table  = (const float*)d_in[3];
    const float* W1 = (const float*)d_in[4];
    const float* b1 = (const float*)d_in[5];
    const float* W2 = (const float*)d_in[6];
    const float* b2 = (const float*)d_in[7];
    const float* W3 = (const float*)d_in[8];
    const float* b3 = (const float*)d_in[9];
    float* out = (float*)d_out;

    const int N = in_sizes[0];
    const int E = in_sizes[1] / 2;
    const int* row = edge_index;        // edge_index[0, :]
    const int* col = edge_index + E;    // edge_index[1, :]

    float* bufA; cudaGetSymbolAddress((void**)&bufA, g_bufA);
    float* bufB; cudaGetSymbolAddress((void**)&bufB, g_bufB);
    float* bufC; cudaGetSymbolAddress((void**)&bufC, g_bufC);
    int*   degi; cudaGetSymbolAddress((void**)&degi, g_degi);
    float* pool; cudaGetSymbolAddress((void**)&pool, g_pool);
    float* cnt;  cudaGetSymbolAddress((void**)&cnt,  g_cnt);

    const int T = 256;
    const int scanB = (N + 1023) / 1024;

    // ---- precompute: degrees (+dinv), CSR-by-destination ----
    cudaMemsetAsync(degi, 0, N * sizeof(int));
    cudaMemsetAsync(pool, 0, G * D * sizeof(float));
    cudaMemsetAsync(cnt,  0, G * sizeof(float));
    k_hist <<<(E + T - 1) / T, T>>>(col, E);
    k_scan1<<<scanB, 256>>>(N);
    k_scan2<<<1, 256>>>(scanB);
    k_scan3<<<(N + T - 1) / T, T>>>(N, E);
    k_build<<<(E + T - 1) / T, T>>>(row, col, E);

    int mm_blocks  = (N + 15) / 16;
    int agg_blocks = (N + 7) / 8;       // 8 warps/block, warp per node

    // layer 1: emb-gather -> hs(B); agg -> y(C)   [k_mm here is kernel #6 -> ncu]
    k_mm <<<mm_blocks, T>>>(nullptr, node_types, emb_table, W1, bufB, N, 0);
    k_agg<<<agg_blocks, T>>>(bufB, b1, bufC, N);
    // layer 2: relu(C) -> hs(B); agg -> y(A)
    k_mm <<<mm_blocks, T>>>(bufC, nullptr, nullptr, W2, bufB, N, 1);
    k_agg<<<agg_blocks, T>>>(bufB, b2, bufA, N);
    // layer 3: relu(A) -> hs(B); agg -> y(C)
    k_mm <<<mm_blocks, T>>>(bufA, nullptr, nullptr, W3, bufB, N, 1);
    k_agg<<<agg_blocks, T>>>(bufB, b3, bufC, N);

    // mean-pool + L2 normalize
    k_pool <<<(N + POOL_CHUNK - 1) / POOL_CHUNK, 64>>>(bufC, batch, N);
    k_final<<<2, 1024>>>(out);
}

// round 11
// speedup vs baseline: 3.3507x; 1.3092x over previous
#include <cuda_runtime.h>

// Problem constants (fixed by the dataset)
#define NMAX 100000
#define EMAX 1600000
#define D    64
#define G    64

// ---- device scratch (no allocations allowed) ----
__device__ int   g_degi  [NMAX];        // in-degree (real edges only)
__device__ float g_dinv  [NMAX];        // rsqrt(deg+1)
__device__ int   g_off   [NMAX + 1];    // CSR row offsets (by destination)
__device__ int   g_cursor[NMAX];        // build cursors
__device__ int   g_bsum  [256];         // scan block partials
__device__ int   g_csrc  [EMAX];        // CSR: source node per edge slot
__device__ float g_bufA  [NMAX * D];
__device__ float g_bufB  [NMAX * D];    // hs = (x@W)*dinv
__device__ float g_bufC  [NMAX * D];
__device__ float g_pool  [G * D];
__device__ float g_cnt   [G];

// ------------------------------------------------------------------
// K_hist: in-degree histogram over edge targets (col)
// ------------------------------------------------------------------
__global__ void k_hist(const int* __restrict__ col, int E) {
    int e = blockIdx.x * blockDim.x + threadIdx.x;
    if (e < E) atomicAdd(&g_degi[col[e]], 1);
}

// ------------------------------------------------------------------
// Scan pass 1: per-block (1024 elems) exclusive scan of g_degi -> g_off,
//              block totals -> g_bsum. Also computes dinv = rsqrt(deg+1).
// ------------------------------------------------------------------
__global__ void k_scan1(int N) {
    __shared__ int sh[256];
    int t = threadIdx.x;
    int base = blockIdx.x * 1024;
    int v[4];
    int sum = 0;
#pragma unroll
    for (int j = 0; j < 4; j++) {
        int idx = base + t * 4 + j;
        v[j] = (idx < N) ? g_degi[idx] : 0;
        if (idx < N) g_dinv[idx] = rsqrtf((float)(v[j] + 1));
        sum += v[j];
    }
    sh[t] = sum;
    __syncthreads();
    for (int o = 1; o < 256; o <<= 1) {
        int x = (t >= o) ? sh[t - o] : 0;
        __syncthreads();
        sh[t] += x;
        __syncthreads();
    }
    int excl = sh[t] - sum;
    if (t == 255) g_bsum[blockIdx.x] = sh[255];
    int run = excl;
#pragma unroll
    for (int j = 0; j < 4; j++) {
        int idx = base + t * 4 + j;
        if (idx < N) g_off[idx] = run;
        run += v[j];
    }
}

// ------------------------------------------------------------------
// Scan pass 2: single block exclusive-scans the block partials (B <= 256)
// ------------------------------------------------------------------
__global__ void k_scan2(int B) {
    __shared__ int sh[256];
    int t = threadIdx.x;
    int v = (t < B) ? g_bsum[t] : 0;
    sh[t] = v;
    __syncthreads();
    for (int o = 1; o < 256; o <<= 1) {
        int x = (t >= o) ? sh[t - o] : 0;
        __syncthreads();
        sh[t] += x;
        __syncthreads();
    }
    if (t < B) g_bsum[t] = sh[t] - v;
}

// ------------------------------------------------------------------
// Scan pass 3: add block base, init cursors, set sentinel off[N]=E
// ------------------------------------------------------------------
__global__ void k_scan3(int N, int E) {
    int i = blockIdx.x * blockDim.x + threadIdx.x;
    if (i < N) {
        int o = g_off[i] + g_bsum[i >> 10];
        g_off[i]    = o;
        g_cursor[i] = o;
    }
    if (i == 0) g_off[N] = E;
}

// ------------------------------------------------------------------
// K_build: fill CSR source array via per-destination cursors
// ------------------------------------------------------------------
__global__ void k_build(const int* __restrict__ row, const int* __restrict__ col, int E) {
    int e = blockIdx.x * blockDim.x + threadIdx.x;
    if (e < E) {
        int p = atomicAdd(&g_cursor[col[e]], 1);
        g_csrc[p] = row[e];
    }
}

// ------------------------------------------------------------------
// K_mm v3: hs = (relu?(x) @ W) * dinv  -- register-blocked, FFMA-bound
//   256 threads = 16 row-groups x 16 col-quads; thread computes 4 rows x 4 cols.
//   Per k-quad: 4 W LDS.128 (2 phases each) + 4 x LDS.128 (broadcast, 1 phase)
//   per 64 FFMA -> FFMA issue binds.
//   If nt != nullptr, x row = emb_table[nt[n]] (fused embedding gather).
// ------------------------------------------------------------------
__global__ void __launch_bounds__(256)
k_mm(const float* __restrict__ x, const int* __restrict__ nt,
     const float* __restrict__ emb,
     const float* __restrict__ W,
     float* __restrict__ hs,
     int N, int relu_in) {
    __shared__ float4 sW4[D * 16];      // [k][dq]
    __shared__ float4 sx4[64 * 16];     // [row][kq]
    int tid = threadIdx.x;
    const float4* W4 = (const float4*)W;
    for (int i = tid; i < D * 16; i += 256) sW4[i] = W4[i];

    int base = blockIdx.x * 64;
    for (int t4 = tid; t4 < 64 * 16; t4 += 256) {
        int r  = t4 >> 4;
        int kq = t4 & 15;
        int n  = base + r;
        float4 v = make_float4(0.f, 0.f, 0.f, 0.f);
        if (n < N) {
            const float4* src = nt ? ((const float4*)emb + (long long)nt[n] * 16)
                                   : ((const float4*)x + (long long)n * 16);
            v = src[kq];
            if (relu_in) {
                v.x = fmaxf(v.x, 0.f); v.y = fmaxf(v.y, 0.f);
                v.z = fmaxf(v.z, 0.f); v.w = fmaxf(v.w, 0.f);
            }
        }
        sx4[t4] = v;
    }
    __syncthreads();

    int dq = tid & 15;     // column quad 0..15
    int rg = tid >> 4;     // row group 0..15 -> rows rg*4 .. rg*4+3
    int n0 = base + rg * 4;

    float4 a0 = make_float4(0.f,0.f,0.f,0.f);
    float4 a1 = make_float4(0.f,0.f,0.f,0.f);
    float4 a2 = make_float4(0.f,0.f,0.f,0.f);
    float4 a3 = make_float4(0.f,0.f,0.f,0.f);

#pragma unroll
    for (int kq = 0; kq < 16; kq++) {
        float4 w0 = sW4[(kq * 4 + 0) * 16 + dq];
        float4 w1 = sW4[(kq * 4 + 1) * 16 + dq];
        float4 w2 = sW4[(kq * 4 + 2) * 16 + dq];
        float4 w3 = sW4[(kq * 4 + 3) * 16 + dq];
#pragma unroll
        for (int r = 0; r < 4; r++) {
            float4 xv = sx4[(rg * 4 + r) * 16 + kq];
            float4* a = (r == 0) ? &a0 : (r == 1) ? &a1 : (r == 2) ? &a2 : &a3;
            a->x = fmaf(xv.x, w0.x, a->x); a->y = fmaf(xv.x, w0.y, a->y);
            a->z = fmaf(xv.x, w0.z, a->z); a->w = fmaf(xv.x, w0.w, a->w);
            a->x = fmaf(xv.y, w1.x, a->x); a->y = fmaf(xv.y, w1.y, a->y);
            a->z = fmaf(xv.y, w1.z, a->z); a->w = fmaf(xv.y, w1.w, a->w);
            a->x = fmaf(xv.z, w2.x, a->x); a->y = fmaf(xv.z, w2.y, a->y);
            a->z = fmaf(xv.z, w2.z, a->z); a->w = fmaf(xv.z, w2.w, a->w);
            a->x = fmaf(xv.w, w3.x, a->x); a->y = fmaf(xv.w, w3.y, a->y);
            a->z = fmaf(xv.w, w3.z, a->z); a->w = fmaf(xv.w, w3.w, a->w);
        }
    }

    float4* H4 = (float4*)hs;
#pragma unroll
    for (int r = 0; r < 4; r++) {
        int n = n0 + r;
        if (n < N) {
            float di = g_dinv[n];
            float4 a = (r == 0) ? a0 : (r == 1) ? a1 : (r == 2) ? a2 : a3;
            a.x *= di; a.y *= di; a.z *= di; a.w *= di;
            H4[(long long)n * 16 + dq] = a;
        }
    }
}

// ------------------------------------------------------------------
// K_agg v3: y[n] = b + dinv[n] * ( sum_{src in in(n)} hs[src] + hs[n] )
//   warp per node, float2 per lane; 8/4/1 laddered unroll (MLP up to 8),
//   4 independent accumulator chains. Pure gather + coalesced store.
// ------------------------------------------------------------------
__global__ void __launch_bounds__(256)
k_agg(const float* __restrict__ hs, const float* __restrict__ b,
      float* __restrict__ y, int N) {
    int w    = (blockIdx.x * blockDim.x + threadIdx.x) >> 5;
    int lane = threadIdx.x & 31;
    if (w >= N) return;
    int i   = g_off[w];
    int end = g_off[w + 1];
    const float2* H = (const float2*)hs;

    // hoist epilogue operands so their latency overlaps the gather loop
    float2 hv = H[(long long)w * 32 + lane];
    float  di = g_dinv[w];
    float  bx = b[lane * 2];
    float  by = b[lane * 2 + 1];

    float ax0 = 0.f, ay0 = 0.f, ax1 = 0.f, ay1 = 0.f;
    float ax2 = 0.f, ay2 = 0.f, ax3 = 0.f, ay3 = 0.f;

    for (; i + 7 < end; i += 8) {
        int s0 = __ldg(&g_csrc[i]);
        int s1 = __ldg(&g_csrc[i + 1]);
        int s2 = __ldg(&g_csrc[i + 2]);
        int s3 = __ldg(&g_csrc[i + 3]);
        int s4 = __ldg(&g_csrc[i + 4]);
        int s5 = __ldg(&g_csrc[i + 5]);
        int s6 = __ldg(&g_csrc[i + 6]);
        int s7 = __ldg(&g_csrc[i + 7]);
        float2 v0 = H[(long long)s0 * 32 + lane];
        float2 v1 = H[(long long)s1 * 32 + lane];
        float2 v2 = H[(long long)s2 * 32 + lane];
        float2 v3 = H[(long long)s3 * 32 + lane];
        float2 v4 = H[(long long)s4 * 32 + lane];
        float2 v5 = H[(long long)s5 * 32 + lane];
        float2 v6 = H[(long long)s6 * 32 + lane];
        float2 v7 = H[(long long)s7 * 32 + lane];
        ax0 += v0.x + v1.x;  ay0 += v0.y + v1.y;
        ax1 += v2.x + v3.x;  ay1 += v2.y + v3.y;
        ax2 += v4.x + v5.x;  ay2 += v4.y + v5.y;
        ax3 += v6.x + v7.x;  ay3 += v6.y + v7.y;
    }
    for (; i + 3 < end; i += 4) {
        int s0 = __ldg(&g_csrc[i]);
        int s1 = __ldg(&g_csrc[i + 1]);
        int s2 = __ldg(&g_csrc[i + 2]);
        int s3 = __ldg(&g_csrc[i + 3]);
        float2 v0 = H[(long long)s0 * 32 + lane];
        float2 v1 = H[(long long)s1 * 32 + lane];
        float2 v2 = H[(long long)s2 * 32 + lane];
        float2 v3 = H[(long long)s3 * 32 + lane];
        ax0 += v0.x + v1.x;  ay0 += v0.y + v1.y;
        ax1 += v2.x + v3.x;  ay1 += v2.y + v3.y;
    }
    for (; i < end; i++) {
        int s = __ldg(&g_csrc[i]);
        float2 v = H[(long long)s * 32 + lane];
        ax2 += v.x;  ay2 += v.y;
    }

    float2 o;
    o.x = bx + di * ((ax0 + ax1) + (ax2 + ax3) + hv.x);
    o.y = by + di * ((ay0 + ay1) + (ay2 + ay3) + hv.y);
    ((float2*)y)[(long long)w * 32 + lane] = o;
}

// ------------------------------------------------------------------
// K_pool: segment mean accumulation (batch is sorted -> register-accumulate,
//         flush to global on graph change). 64 threads/block.
// ------------------------------------------------------------------
#define POOL_CHUNK 256
__global__ void k_pool(const float* __restrict__ x, const int* __restrict__ batch, int N) {
    int d = threadIdx.x;              // 0..63
    int s = blockIdx.x * POOL_CHUNK;
    int eN = min(s + POOL_CHUNK, N);
    float acc = 0.0f, cnt = 0.0f;
    int cur = -1;
    for (int n = s; n < eN; n++) {
        int bg = batch[n];
        if (bg != cur) {
            if (cur >= 0) {
                atomicAdd(&g_pool[cur * D + d], acc);
                if (d == 0) atomicAdd(&g_cnt[cur], cnt);
            }
            cur = bg; acc = 0.0f; cnt = 0.0f;
        }
        acc += x[n * D + d];
        cnt += 1.0f;
    }
    if (cur >= 0) {
        atomicAdd(&g_pool[cur * D + d], acc);
        if (d == 0) atomicAdd(&g_cnt[cur], cnt);
    }
}

// ------------------------------------------------------------------
// K_final: pooled = sum/max(cnt,1); out = pooled / ||pooled||_2
// ------------------------------------------------------------------
__global__ void k_final(float* __restrict__ out) {
    int r    = blockIdx.x * 32 + (threadIdx.x >> 5);
    int lane = threadIdx.x & 31;
    float c  = fmaxf(g_cnt[r], 1.0f);
    float v0 = g_pool[r * D + lane]      / c;
    float v1 = g_pool[r * D + 32 + lane] / c;
    float ss = v0 * v0 + v1 * v1;
#pragma unroll
    for (int o = 16; o > 0; o >>= 1) ss += __shfl_xor_sync(0xFFFFFFFFu, ss, o);
    float inv = rsqrtf(ss);
    out[r * D + lane]      = v0 * inv;
    out[r * D + 32 + lane] = v1 * inv;
}

// ------------------------------------------------------------------
// Host launcher
// ------------------------------------------------------------------
extern "C" void kernel_launch(void* const* d_in, const int* in_sizes, int n_in,
                              void* d_out, int out_size) {
    const int*   node_types = (const int*)  d_in[0];
    const int*   edge_index = (const int*)  d_in[1];
    const int*   batch      = (const int*)  d_in[2];
    const float* emb_table  = (const float*)d_in[3];
    const float* W1 = (const float*)d_in[4];
    const float* b1 = (const float*)d_in[5];
    const float* W2 = (const float*)d_in[6];
    const float* b2 = (const float*)d_in[7];
    const float* W3 = (const float*)d_in[8];
    const float* b3 = (const float*)d_in[9];
    float* out = (float*)d_out;

    const int N = in_sizes[0];
    const int E = in_sizes[1] / 2;
    const int* row = edge_index;        // edge_index[0, :]
    const int* col = edge_index + E;    // edge_index[1, :]

    float* bufA; cudaGetSymbolAddress((void**)&bufA, g_bufA);
    float* bufB; cudaGetSymbolAddress((void**)&bufB, g_bufB);
    float* bufC; cudaGetSymbolAddress((void**)&bufC, g_bufC);
    int*   degi; cudaGetSymbolAddress((void**)&degi, g_degi);
    float* pool; cudaGetSymbolAddress((void**)&pool, g_pool);
    float* cnt;  cudaGetSymbolAddress((void**)&cnt,  g_cnt);

    const int T = 256;
    const int scanB = (N + 1023) / 1024;

    cudaMemsetAsync(degi, 0, N * sizeof(int));
    cudaMemsetAsync(pool, 0, G * D * sizeof(float));
    cudaMemsetAsync(cnt,  0, G * sizeof(float));

    int mm_blocks  = (N + 63) / 64;
    int agg_blocks = (N + 7) / 8;       // 8 warps/block, warp per node

    // ---- precompute + layer-1 mm interleaved so mm1 is the 4th kernel (-> ncu)
    k_hist <<<(E + T - 1) / T, T>>>(col, E);                              // 1
    k_scan1<<<scanB, 256>>>(N);                                           // 2
    k_scan2<<<1, 256>>>(scanB);                                           // 3
    k_mm   <<<mm_blocks, T>>>(nullptr, node_types, emb_table, W1, bufB, N, 0); // 4 <- profiled
    k_scan3<<<(N + T - 1) / T, T>>>(N, E);                                // 5
    k_build<<<(E + T - 1) / T, T>>>(row, col, E);                         // 6

    // layer 1 aggregation
    k_agg<<<agg_blocks, T>>>(bufB, b1, bufC, N);
    // layer 2
    k_mm <<<mm_blocks, T>>>(bufC, nullptr, nullptr, W2, bufB, N, 1);
    k_agg<<<agg_blocks, T>>>(bufB, b2, bufA, N);
    // layer 3
    k_mm <<<mm_blocks, T>>>(bufA, nullptr, nullptr, W3, bufB, N, 1);
    k_agg<<<agg_blocks, T>>>(bufB, b3, bufC, N);

    // mean-pool + L2 normalize
    k_pool <<<(N + POOL_CHUNK - 1) / POOL_CHUNK, 64>>>(bufC, batch, N);
    k_final<<<2, 1024>>>(out);
}